// round 4
// baseline (speedup 1.0000x reference)
#include <cuda_runtime.h>
#include <cstddef>
#include <cstdint>

#define NN 50000
#define NE 400000
#define DD 128

// Scratch (device globals: allocation-free rule)
__device__ float g_K[NN * DD];
__device__ float g_Q[NN * DD];
__device__ float g_V[NN * DD];
__device__ float g_H[NN * DD];
__device__ int   g_is32;

struct GemmArgs {
    const float* W[4];
    float*       dst[4];   // dst[0..2] = K,Q,V ; dst[3] = skip accumulator
    const float* bias;     // added to dst[3]
};

// ---------------------------------------------------------------------------
// int32-vs-int64 edge_index detection (odd 32-bit words all zero => int64).
// ---------------------------------------------------------------------------
__global__ void detect_init_kernel() { g_is32 = 0; }

__global__ void detect_kernel(const unsigned int* __restrict__ w) {
    int i = blockIdx.x * blockDim.x + threadIdx.x;
    if (i >= NE) return;
    if (w[2 * i + 1] != 0u) atomicOr(&g_is32, 1);
}

// ---------------------------------------------------------------------------
// Fused 4-way projection GEMM using packed fma.rn.f32x2 (FFMA2).
//   dst[w] = act(A) @ W[w],  w = 0..3 ; dst[3] += bias (skip path)
// BM=128, BN=128(=D), BK=16. 256 threads, 8x8 micro-tile per thread.
// A stored in smem PRE-DUPLICATED as float2{a,a} so the FFMA2 broadcast
// operand needs no per-iteration packing. B read as natural f32x2 pairs.
// grid = (ceil(N/128), 4)
// ---------------------------------------------------------------------------
#define BM 128
#define BK 16

typedef unsigned long long u64;

__device__ __forceinline__ u64 ffma2(u64 a, u64 b, u64 c) {
    u64 d;
    asm("fma.rn.f32x2 %0, %1, %2, %3;" : "=l"(d) : "l"(a), "l"(b), "l"(c));
    return d;
}

__global__ void __launch_bounds__(256, 2) gemm4_kernel(
    const float* __restrict__ A, GemmArgs ga, int apply_relu)
{
    __shared__ float2 AsD[BM][BK + 1];   // [row][k], value duplicated {a,a}
    __shared__ float  Bs[BK][DD + 4];    // [k][col]

    const int w = blockIdx.y;
    const float* __restrict__ W = ga.W[w];
    float* __restrict__ dst = ga.dst[w];

    const int row0 = blockIdx.x * BM;
    const int t  = threadIdx.x;
    const int tx = t & 15;        // column group: cols tx*8 .. tx*8+7
    const int ty = t >> 4;        // row group:    rows ty*8 .. ty*8+7

    u64 acc[8][4];                // 8 rows x 4 f32x2 col-pairs
    #pragma unroll
    for (int i = 0; i < 8; i++)
        #pragma unroll
        for (int j = 0; j < 4; j++) acc[i][j] = 0ull;   // bitwise {0.f,0.f}

    for (int k0 = 0; k0 < DD; k0 += BK) {
        // ---- Load A tile (128 x 16): 512 float4, 2 per thread ----
        #pragma unroll
        for (int l = 0; l < 2; l++) {
            int idx = l * 256 + t;            // float4 index
            int r   = idx >> 2;               // row in tile (4 float4 per row)
            int c4  = (idx & 3) * 4;          // k offset
            int grow = row0 + r;
            float4 v = make_float4(0.f, 0.f, 0.f, 0.f);
            if (grow < NN) v = *(const float4*)&A[(size_t)grow * DD + k0 + c4];
            if (apply_relu) {
                v.x = fmaxf(v.x, 0.f); v.y = fmaxf(v.y, 0.f);
                v.z = fmaxf(v.z, 0.f); v.w = fmaxf(v.w, 0.f);
            }
            AsD[r][c4 + 0] = make_float2(v.x, v.x);
            AsD[r][c4 + 1] = make_float2(v.y, v.y);
            AsD[r][c4 + 2] = make_float2(v.z, v.z);
            AsD[r][c4 + 3] = make_float2(v.w, v.w);
        }
        // ---- Load B tile (16 x 128): 512 float4, 2 per thread ----
        #pragma unroll
        for (int l = 0; l < 2; l++) {
            int idx = l * 256 + t;
            int r   = idx >> 5;               // k row (32 float4 per row)
            int c4  = (idx & 31) * 4;
            float4 v = *(const float4*)&W[(size_t)(k0 + r) * DD + c4];
            *(float4*)&Bs[r][c4] = v;
        }
        __syncthreads();

        #pragma unroll
        for (int kk = 0; kk < BK; kk++) {
            u64 a[8], b[4];
            #pragma unroll
            for (int i = 0; i < 8; i++)
                a[i] = *(const u64*)&AsD[ty * 8 + i][kk];
            const float* brow = &Bs[kk][tx * 8];
            #pragma unroll
            for (int j = 0; j < 4; j++)
                b[j] = *(const u64*)&brow[2 * j];
            #pragma unroll
            for (int i = 0; i < 8; i++)
                #pragma unroll
                for (int j = 0; j < 4; j++)
                    acc[i][j] = ffma2(a[i], b[j], acc[i][j]);
        }
        __syncthreads();
    }

    // ---- Epilogue ----
    const bool add_bias = (w == 3);
    float bias8[8];
    if (add_bias) {
        #pragma unroll
        for (int j = 0; j < 8; j++) bias8[j] = ga.bias[tx * 8 + j];
    }

    union { u64 u; float2 f; } cv;
    #pragma unroll
    for (int i = 0; i < 8; i++) {
        int grow = row0 + ty * 8 + i;
        if (grow >= NN) break;
        float o[8];
        #pragma unroll
        for (int j = 0; j < 4; j++) {
            cv.u = acc[i][j];
            o[2 * j]     = cv.f.x;
            o[2 * j + 1] = cv.f.y;
        }
        if (add_bias) {
            #pragma unroll
            for (int j = 0; j < 8; j++) o[j] += bias8[j];
        }
        float* dp = &dst[(size_t)grow * DD + tx * 8];
        *(float4*)&dp[0] = make_float4(o[0], o[1], o[2], o[3]);
        *(float4*)&dp[4] = make_float4(o[4], o[5], o[6], o[7]);
    }
}

// ---------------------------------------------------------------------------
// Edge kernel: one warp per edge, lane handles 4 consecutive features.
//   eta = sigmoid(K[tgt] + Q[src]); msg = eta * V[src]; red.v4 into out[tgt]
// ---------------------------------------------------------------------------
__global__ void __launch_bounds__(256) edge_kernel(
    const void* __restrict__ edge_index,
    const float* __restrict__ K, const float* __restrict__ Q,
    const float* __restrict__ V, float* __restrict__ out)
{
    int warp = (blockIdx.x * blockDim.x + threadIdx.x) >> 5;
    if (warp >= NE) return;
    int lane = threadIdx.x & 31;

    int src, tgt;
    if (g_is32) {
        const int* ei = (const int*)edge_index;
        src = ei[warp];
        tgt = ei[NE + warp];
    } else {
        const long long* ei = (const long long*)edge_index;
        src = (int)ei[warp];
        tgt = (int)ei[NE + warp];
    }

    int d0 = lane * 4;
    float4 kt = *(const float4*)&K[(size_t)tgt * DD + d0];
    float4 qs = *(const float4*)&Q[(size_t)src * DD + d0];
    float4 vs = *(const float4*)&V[(size_t)src * DD + d0];

    float4 m;
    m.x = vs.x / (1.f + __expf(-(kt.x + qs.x)));
    m.y = vs.y / (1.f + __expf(-(kt.y + qs.y)));
    m.z = vs.z / (1.f + __expf(-(kt.z + qs.z)));
    m.w = vs.w / (1.f + __expf(-(kt.w + qs.w)));

    float* o = &out[(size_t)tgt * DD + d0];
    asm volatile("red.global.add.v4.f32 [%0], {%1, %2, %3, %4};"
                 :: "l"(o), "f"(m.x), "f"(m.y), "f"(m.z), "f"(m.w)
                 : "memory");
}

// ---------------------------------------------------------------------------
extern "C" void kernel_launch(void* const* d_in, const int* in_sizes, int n_in,
                              void* d_out, int out_size)
{
    const float* x   = (const float*)d_in[0];
    const void*  ei  = d_in[1];
    const float* Wk1 = (const float*)d_in[2];
    const float* Wq1 = (const float*)d_in[3];
    const float* Wv1 = (const float*)d_in[4];
    const float* Ws1 = (const float*)d_in[5];
    const float* b1  = (const float*)d_in[6];
    const float* Wk2 = (const float*)d_in[7];
    const float* Wq2 = (const float*)d_in[8];
    const float* Wv2 = (const float*)d_in[9];
    const float* Ws2 = (const float*)d_in[10];
    const float* b2  = (const float*)d_in[11];
    float* out = (float*)d_out;

    float *pK, *pQ, *pV, *pH;
    cudaGetSymbolAddress((void**)&pK, g_K);
    cudaGetSymbolAddress((void**)&pQ, g_Q);
    cudaGetSymbolAddress((void**)&pV, g_V);
    cudaGetSymbolAddress((void**)&pH, g_H);

    detect_init_kernel<<<1, 1>>>();
    detect_kernel<<<(NE + 255) / 256, 256>>>((const unsigned int*)ei);

    dim3 ggrid((NN + BM - 1) / BM, 4);
    dim3 egrid((NE * 32 + 255) / 256);

    // ---- Layer 1 ----
    GemmArgs g1;
    g1.W[0] = Wk1; g1.W[1] = Wq1; g1.W[2] = Wv1; g1.W[3] = Ws1;
    g1.dst[0] = pK; g1.dst[1] = pQ; g1.dst[2] = pV; g1.dst[3] = pH;
    g1.bias = b1;
    gemm4_kernel<<<ggrid, 256>>>(x, g1, /*relu=*/0);
    edge_kernel<<<egrid, 256>>>(ei, pK, pQ, pV, pH);

    // ---- Layer 2 (ReLU fused into A-load) ----
    GemmArgs g2;
    g2.W[0] = Wk2; g2.W[1] = Wq2; g2.W[2] = Wv2; g2.W[3] = Ws2;
    g2.dst[0] = pK; g2.dst[1] = pQ; g2.dst[2] = pV; g2.dst[3] = out;
    g2.bias = b2;
    gemm4_kernel<<<ggrid, 256>>>(pH, g2, /*relu=*/1);
    edge_kernel<<<egrid, 256>>>(ei, pK, pQ, pV, out);
}

// round 6
// speedup vs baseline: 1.1449x; 1.1449x over previous
#include <cuda_runtime.h>
#include <cuda_bf16.h>
#include <cstdint>
#include <cstddef>

#define NN 50000
#define NE 400000
#define DD 128

// Scratch (device globals: allocation-free rule)
__device__ float g_K[NN * DD];
__device__ float g_Q[NN * DD];
__device__ float g_V[NN * DD];
__device__ float g_H[NN * DD];
__device__ __nv_bfloat16 g_Bs[8 * 256 * 128];   // split weights: [w][khi|klo][n]
__device__ int   g_is32;

struct OutArgs {
    float*       dst[4];   // dst[0..2] = K,Q,V ; dst[3] = skip accumulator
    const float* bias;     // added to dst[3]
};
struct PrepArgs { const float* W[8]; };

// ---------------------------------------------------------------------------
// int32-vs-int64 edge_index detection (odd 32-bit words all zero => int64).
// ---------------------------------------------------------------------------
__global__ void detect_init_kernel() { g_is32 = 0; }
__global__ void detect_kernel(const unsigned int* __restrict__ w) {
    int i = blockIdx.x * blockDim.x + threadIdx.x;
    if (i >= NE) return;
    if (w[2 * i + 1] != 0u) atomicOr(&g_is32, 1);
}

// ---------------------------------------------------------------------------
// bf16 split: v = hi + lo (+ O(2^-16 |v|))
// ---------------------------------------------------------------------------
__device__ __forceinline__ void split4(float4 v, uint2& hi, uint2& lo) {
    __nv_bfloat16 hx = __float2bfloat16(v.x);
    __nv_bfloat16 hy = __float2bfloat16(v.y);
    __nv_bfloat16 hz = __float2bfloat16(v.z);
    __nv_bfloat16 hw = __float2bfloat16(v.w);
    __nv_bfloat16 lx = __float2bfloat16(v.x - __bfloat162float(hx));
    __nv_bfloat16 ly = __float2bfloat16(v.y - __bfloat162float(hy));
    __nv_bfloat16 lz = __float2bfloat16(v.z - __bfloat162float(hz));
    __nv_bfloat16 lw = __float2bfloat16(v.w - __bfloat162float(hw));
    hi.x = (uint32_t)__bfloat16_as_ushort(hx) | ((uint32_t)__bfloat16_as_ushort(hy) << 16);
    hi.y = (uint32_t)__bfloat16_as_ushort(hz) | ((uint32_t)__bfloat16_as_ushort(hw) << 16);
    lo.x = (uint32_t)__bfloat16_as_ushort(lx) | ((uint32_t)__bfloat16_as_ushort(ly) << 16);
    lo.y = (uint32_t)__bfloat16_as_ushort(lz) | ((uint32_t)__bfloat16_as_ushort(lw) << 16);
}

// ---------------------------------------------------------------------------
// Weight prep: split each W[k][n] (f32) into g_Bs[w]: rows 0..127 = bf16 hi(k),
// rows 128..255 = bf16 lo(k), n contiguous.  8 blocks (one per weight).
// ---------------------------------------------------------------------------
__global__ void __launch_bounds__(256) prep_weights(PrepArgs pa) {
    const int w = blockIdx.x;
    const float* __restrict__ W = pa.W[w];
    __nv_bfloat16* __restrict__ out = g_Bs + (size_t)w * 256 * 128;
    const int t = threadIdx.x;
    #pragma unroll 4
    for (int l = 0; l < 16; l++) {
        int idx = l * 256 + t;
        int k = idx >> 5;
        int c4 = (idx & 31) * 4;
        float4 v = *(const float4*)&W[(size_t)k * DD + c4];
        uint2 hi, lo;
        split4(v, hi, lo);
        *(uint2*)&out[(size_t)k * 128 + c4]         = hi;
        *(uint2*)&out[(size_t)(128 + k) * 128 + c4] = lo;
    }
}

// ---------------------------------------------------------------------------
// HMMA helpers
// ---------------------------------------------------------------------------
__device__ __forceinline__ uint32_t smem_u32(const void* p) {
    uint32_t a;
    asm("{ .reg .u64 t; cvta.to.shared.u64 t, %1; cvt.u32.u64 %0, t; }"
        : "=r"(a) : "l"(p));
    return a;
}

__device__ __forceinline__ void ldsm4(uint32_t* r, uint32_t addr) {
    asm volatile("ldmatrix.sync.aligned.m8n8.x4.shared.b16 {%0,%1,%2,%3}, [%4];"
        : "=r"(r[0]), "=r"(r[1]), "=r"(r[2]), "=r"(r[3]) : "r"(addr));
}
__device__ __forceinline__ void ldsm4t(uint32_t* r, uint32_t addr) {
    asm volatile("ldmatrix.sync.aligned.m8n8.x4.trans.shared.b16 {%0,%1,%2,%3}, [%4];"
        : "=r"(r[0]), "=r"(r[1]), "=r"(r[2]), "=r"(r[3]) : "r"(addr));
}
__device__ __forceinline__ void mma16816(float* d, const uint32_t* a, const uint32_t* b) {
    asm volatile(
        "mma.sync.aligned.m16n8k16.row.col.f32.bf16.bf16.f32 "
        "{%0,%1,%2,%3}, {%4,%5,%6,%7}, {%8,%9}, {%0,%1,%2,%3};"
        : "+f"(d[0]), "+f"(d[1]), "+f"(d[2]), "+f"(d[3])
        : "r"(a[0]), "r"(a[1]), "r"(a[2]), "r"(a[3]), "r"(b[0]), "r"(b[1]));
}

// smem strides (in bf16 elements); padded for conflict-free ldmatrix
#define AS 264    // A_s: 128 rows x 256 k
#define BS 136    // B_s: 256 k  x 128 n
#define SMEM_A_ELEMS (128 * AS)
#define SMEM_B_ELEMS (256 * BS)
#define SMEM_BYTES   ((SMEM_A_ELEMS + SMEM_B_ELEMS) * 2 + 512)

// ---------------------------------------------------------------------------
// Tensor-core (mma.sync bf16x3) 4-way projection GEMM.
//   dst[w] = act(A) @ W[w], w=0..3 ; dst[3] += bias
// One CTA = 128 rows, loops over 4 weights. grid = ceil(NN/128), 256 threads.
// ---------------------------------------------------------------------------
__global__ void __launch_bounds__(256, 1) gemm_hmma_kernel(
    const float* __restrict__ A, const __nv_bfloat16* __restrict__ Bsp,
    OutArgs oa, int apply_relu)
{
    extern __shared__ char smem[];
    __nv_bfloat16* A_s = (__nv_bfloat16*)smem;
    __nv_bfloat16* B_s = A_s + SMEM_A_ELEMS;
    float* bias_s = (float*)(B_s + SMEM_B_ELEMS);

    const int t = threadIdx.x;
    const int wid = t >> 5;
    const int ln = t & 31;
    const int rg = wid & 3;        // row group: rows rg*32 .. +31
    const int cg = wid >> 2;       // col group: cols cg*64 .. +63
    const int row0 = blockIdx.x * 128;

    if (t < 128) bias_s[t] = oa.bias[t];

    // ---- A convert: load f32, optional relu, bf16-split into A_s ----
    #pragma unroll 4
    for (int l = 0; l < 16; l++) {
        int idx = l * 256 + t;
        int r = idx >> 5;
        int c4 = (idx & 31) * 4;
        int grow = row0 + r;
        float4 v = make_float4(0.f, 0.f, 0.f, 0.f);
        if (grow < NN) v = *(const float4*)&A[(size_t)grow * DD + c4];
        if (apply_relu) {
            v.x = fmaxf(v.x, 0.f); v.y = fmaxf(v.y, 0.f);
            v.z = fmaxf(v.z, 0.f); v.w = fmaxf(v.w, 0.f);
        }
        uint2 hi, lo;
        split4(v, hi, lo);
        *(uint2*)&A_s[r * AS + c4]       = hi;
        *(uint2*)&A_s[r * AS + 128 + c4] = lo;
    }

    const uint32_t sbA = smem_u32(A_s);
    const uint32_t sbB = smem_u32(B_s);
    // per-lane ldmatrix base addresses
    const uint32_t a_row = sbA + (uint32_t)(((rg * 32 + (ln & 15)) * AS + (ln >> 4) * 8) * 2);
    const int mat = ln >> 3, rowin = ln & 7;
    const uint32_t b_base = sbB + (uint32_t)(((((mat & 1) * 8 + rowin) * BS)
                                   + cg * 64 + (mat >> 1) * 8) * 2);

    for (int w = 0; w < 4; w++) {
        // ---- Copy split-B for weight w into smem (global bf16 -> padded smem) ----
        const __nv_bfloat16* src = Bsp + (size_t)w * 256 * 128;
        #pragma unroll 4
        for (int l = 0; l < 16; l++) {
            int idx = l * 256 + t;          // uint4 index (8 bf16)
            int r = idx >> 4;
            int q = idx & 15;
            *(uint4*)&B_s[r * BS + q * 8] = *(const uint4*)&src[(size_t)r * 128 + q * 8];
        }
        __syncthreads();

        float ac[2][8][4];
        #pragma unroll
        for (int mi = 0; mi < 2; mi++)
            #pragma unroll
            for (int nt = 0; nt < 8; nt++)
                #pragma unroll
                for (int j = 0; j < 4; j++) ac[mi][nt][j] = 0.f;

        // ---- 3 passes: ahi*bhi, alo*bhi, ahi*blo ----
        #pragma unroll
        for (int pass = 0; pass < 3; pass++) {
            const int kbA = (pass == 1) ? 128 : 0;
            const int kbB = (pass == 2) ? 128 : 0;
            #pragma unroll
            for (int ks = 0; ks < 8; ks++) {
                const int kA = kbA + ks * 16;
                const int kB = kbB + ks * 16;
                uint32_t af[2][4];
                ldsm4(af[0], a_row + (uint32_t)((0 * AS + kA) * 2));
                ldsm4(af[1], a_row + (uint32_t)((16 * AS + kA) * 2));
                uint32_t bf[4][4];
                #pragma unroll
                for (int np = 0; np < 4; np++)
                    ldsm4t(bf[np], b_base + (uint32_t)((kB * BS + np * 16) * 2));
                #pragma unroll
                for (int mi = 0; mi < 2; mi++)
                    #pragma unroll
                    for (int np = 0; np < 4; np++) {
                        mma16816(ac[mi][2 * np],     af[mi], &bf[np][0]);
                        mma16816(ac[mi][2 * np + 1], af[mi], &bf[np][2]);
                    }
            }
        }
        __syncthreads();   // all warps done reading B_s before next copy

        // ---- Epilogue: direct fp32 stores; bias on skip path (w==3) ----
        float* dst = oa.dst[w];
        const int r_base = row0 + rg * 32 + (ln >> 2);
        const int c_base = cg * 64 + (ln & 3) * 2;
        const bool add_bias = (w == 3);
        #pragma unroll
        for (int mi = 0; mi < 2; mi++) {
            const int r_m = r_base + mi * 16;
            #pragma unroll
            for (int nt = 0; nt < 8; nt++) {
                const int c = c_base + nt * 8;
                float b0 = 0.f, b1 = 0.f;
                if (add_bias) { b0 = bias_s[c]; b1 = bias_s[c + 1]; }
                if (r_m < NN)
                    *(float2*)&dst[(size_t)r_m * DD + c] =
                        make_float2(ac[mi][nt][0] + b0, ac[mi][nt][1] + b1);
                if (r_m + 8 < NN)
                    *(float2*)&dst[(size_t)(r_m + 8) * DD + c] =
                        make_float2(ac[mi][nt][2] + b0, ac[mi][nt][3] + b1);
            }
        }
    }
}

// ---------------------------------------------------------------------------
// Edge kernel: one warp per edge, lane handles 4 consecutive features.
//   eta = sigmoid(K[tgt] + Q[src]); msg = eta * V[src]; red.v4 into out[tgt]
// ---------------------------------------------------------------------------
__global__ void __launch_bounds__(256) edge_kernel(
    const void* __restrict__ edge_index,
    const float* __restrict__ K, const float* __restrict__ Q,
    const float* __restrict__ V, float* __restrict__ out)
{
    int warp = (blockIdx.x * blockDim.x + threadIdx.x) >> 5;
    if (warp >= NE) return;
    int lane = threadIdx.x & 31;

    int src, tgt;
    if (g_is32) {
        const int* ei = (const int*)edge_index;
        src = ei[warp];
        tgt = ei[NE + warp];
    } else {
        const long long* ei = (const long long*)edge_index;
        src = (int)ei[warp];
        tgt = (int)ei[NE + warp];
    }

    int d0 = lane * 4;
    float4 kt = *(const float4*)&K[(size_t)tgt * DD + d0];
    float4 qs = *(const float4*)&Q[(size_t)src * DD + d0];
    float4 vs = *(const float4*)&V[(size_t)src * DD + d0];

    float4 m;
    m.x = vs.x / (1.f + __expf(-(kt.x + qs.x)));
    m.y = vs.y / (1.f + __expf(-(kt.y + qs.y)));
    m.z = vs.z / (1.f + __expf(-(kt.z + qs.z)));
    m.w = vs.w / (1.f + __expf(-(kt.w + qs.w)));

    float* o = &out[(size_t)tgt * DD + d0];
    asm volatile("red.global.add.v4.f32 [%0], {%1, %2, %3, %4};"
                 :: "l"(o), "f"(m.x), "f"(m.y), "f"(m.z), "f"(m.w)
                 : "memory");
}

// ---------------------------------------------------------------------------
extern "C" void kernel_launch(void* const* d_in, const int* in_sizes, int n_in,
                              void* d_out, int out_size)
{
    const float* x   = (const float*)d_in[0];
    const void*  ei  = d_in[1];
    const float* Wk1 = (const float*)d_in[2];
    const float* Wq1 = (const float*)d_in[3];
    const float* Wv1 = (const float*)d_in[4];
    const float* Ws1 = (const float*)d_in[5];
    const float* b1  = (const float*)d_in[6];
    const float* Wk2 = (const float*)d_in[7];
    const float* Wq2 = (const float*)d_in[8];
    const float* Wv2 = (const float*)d_in[9];
    const float* Ws2 = (const float*)d_in[10];
    const float* b2  = (const float*)d_in[11];
    float* out = (float*)d_out;

    float *pK, *pQ, *pV, *pH;
    __nv_bfloat16* pBs;
    cudaGetSymbolAddress((void**)&pK, g_K);
    cudaGetSymbolAddress((void**)&pQ, g_Q);
    cudaGetSymbolAddress((void**)&pV, g_V);
    cudaGetSymbolAddress((void**)&pH, g_H);
    cudaGetSymbolAddress((void**)&pBs, g_Bs);

    cudaFuncSetAttribute(gemm_hmma_kernel,
                         cudaFuncAttributeMaxDynamicSharedMemorySize, SMEM_BYTES);

    detect_init_kernel<<<1, 1>>>();
    detect_kernel<<<(NE + 255) / 256, 256>>>((const unsigned int*)ei);

    PrepArgs pa;
    pa.W[0] = Wk1; pa.W[1] = Wq1; pa.W[2] = Wv1; pa.W[3] = Ws1;
    pa.W[4] = Wk2; pa.W[5] = Wq2; pa.W[6] = Wv2; pa.W[7] = Ws2;
    prep_weights<<<8, 256>>>(pa);

    dim3 ggrid((NN + 127) / 128);
    dim3 egrid((NE * 32 + 255) / 256);

    // ---- Layer 1 ----
    OutArgs o1;
    o1.dst[0] = pK; o1.dst[1] = pQ; o1.dst[2] = pV; o1.dst[3] = pH;
    o1.bias = b1;
    gemm_hmma_kernel<<<ggrid, 256, SMEM_BYTES>>>(x, pBs, o1, /*relu=*/0);
    edge_kernel<<<egrid, 256>>>(ei, pK, pQ, pV, pH);

    // ---- Layer 2 (ReLU fused into A convert) ----
    OutArgs o2;
    o2.dst[0] = pK; o2.dst[1] = pQ; o2.dst[2] = pV; o2.dst[3] = out;
    o2.bias = b2;
    gemm_hmma_kernel<<<ggrid, 256, SMEM_BYTES>>>(pH, pBs + (size_t)4 * 256 * 128, o2, /*relu=*/1);
    edge_kernel<<<egrid, 256>>>(ei, pK, pQ, pV, out);
}

// round 7
// speedup vs baseline: 1.5052x; 1.3147x over previous
#include <cuda_runtime.h>
#include <cuda_bf16.h>
#include <cstdint>
#include <cstddef>

#define NN 50000
#define NE 400000
#define DD 128
#define RPC 192                    // rows per CTA

// Scratch (device globals: allocation-free rule)
__device__ float g_K[NN * DD];
__device__ float g_Q[NN * DD];
__device__ float g_V[NN * DD];
__device__ float g_H[NN * DD];
__device__ __nv_bfloat16 g_Bs[8 * 256 * 128];   // split weights: [w][khi|klo][n]
__device__ int   g_is32;

struct OutArgs {
    float*       dst[4];   // dst[0..2] = K,Q,V ; dst[3] = skip accumulator
    const float* bias;     // added to dst[3]
};
struct PrepArgs { const float* W[8]; };

// ---------------------------------------------------------------------------
// int32-vs-int64 edge_index detection (odd 32-bit words all zero => int64).
// ---------------------------------------------------------------------------
__global__ void detect_init_kernel() { g_is32 = 0; }
__global__ void detect_kernel(const unsigned int* __restrict__ w) {
    int i = blockIdx.x * blockDim.x + threadIdx.x;
    if (i >= NE) return;
    if (w[2 * i + 1] != 0u) atomicOr(&g_is32, 1);
}

// ---------------------------------------------------------------------------
// bf16 split: v = hi + lo (+ O(2^-16 |v|))
// ---------------------------------------------------------------------------
__device__ __forceinline__ void split4(float4 v, uint2& hi, uint2& lo) {
    __nv_bfloat16 hx = __float2bfloat16(v.x);
    __nv_bfloat16 hy = __float2bfloat16(v.y);
    __nv_bfloat16 hz = __float2bfloat16(v.z);
    __nv_bfloat16 hw = __float2bfloat16(v.w);
    __nv_bfloat16 lx = __float2bfloat16(v.x - __bfloat162float(hx));
    __nv_bfloat16 ly = __float2bfloat16(v.y - __bfloat162float(hy));
    __nv_bfloat16 lz = __float2bfloat16(v.z - __bfloat162float(hz));
    __nv_bfloat16 lw = __float2bfloat16(v.w - __bfloat162float(hw));
    hi.x = (uint32_t)__bfloat16_as_ushort(hx) | ((uint32_t)__bfloat16_as_ushort(hy) << 16);
    hi.y = (uint32_t)__bfloat16_as_ushort(hz) | ((uint32_t)__bfloat16_as_ushort(hw) << 16);
    lo.x = (uint32_t)__bfloat16_as_ushort(lx) | ((uint32_t)__bfloat16_as_ushort(ly) << 16);
    lo.y = (uint32_t)__bfloat16_as_ushort(lz) | ((uint32_t)__bfloat16_as_ushort(lw) << 16);
}

// ---------------------------------------------------------------------------
// Weight prep: split each W[k][n] (f32) into g_Bs[w]: rows 0..127 = bf16 hi(k),
// rows 128..255 = bf16 lo(k), n contiguous.
// ---------------------------------------------------------------------------
__global__ void __launch_bounds__(256) prep_weights(PrepArgs pa) {
    const int w = blockIdx.x;
    const float* __restrict__ W = pa.W[w];
    __nv_bfloat16* __restrict__ out = g_Bs + (size_t)w * 256 * 128;
    const int t = threadIdx.x;
    #pragma unroll 4
    for (int l = 0; l < 16; l++) {
        int idx = l * 256 + t;
        int k = idx >> 5;
        int c4 = (idx & 31) * 4;
        float4 v = *(const float4*)&W[(size_t)k * DD + c4];
        uint2 hi, lo;
        split4(v, hi, lo);
        *(uint2*)&out[(size_t)k * 128 + c4]         = hi;
        *(uint2*)&out[(size_t)(128 + k) * 128 + c4] = lo;
    }
}

// ---------------------------------------------------------------------------
// HMMA helpers
// ---------------------------------------------------------------------------
__device__ __forceinline__ uint32_t smem_u32(const void* p) {
    uint32_t a;
    asm("{ .reg .u64 t; cvta.to.shared.u64 t, %1; cvt.u32.u64 %0, t; }"
        : "=r"(a) : "l"(p));
    return a;
}

__device__ __forceinline__ void ldsm4(uint32_t* r, uint32_t addr) {
    asm volatile("ldmatrix.sync.aligned.m8n8.x4.shared.b16 {%0,%1,%2,%3}, [%4];"
        : "=r"(r[0]), "=r"(r[1]), "=r"(r[2]), "=r"(r[3]) : "r"(addr));
}
__device__ __forceinline__ void ldsm4t(uint32_t* r, uint32_t addr) {
    asm volatile("ldmatrix.sync.aligned.m8n8.x4.trans.shared.b16 {%0,%1,%2,%3}, [%4];"
        : "=r"(r[0]), "=r"(r[1]), "=r"(r[2]), "=r"(r[3]) : "r"(addr));
}
__device__ __forceinline__ void mma16816(float* d, const uint32_t* a, const uint32_t* b) {
    asm volatile(
        "mma.sync.aligned.m16n8k16.row.col.f32.bf16.bf16.f32 "
        "{%0,%1,%2,%3}, {%4,%5,%6,%7}, {%8,%9}, {%0,%1,%2,%3};"
        : "+f"(d[0]), "+f"(d[1]), "+f"(d[2]), "+f"(d[3])
        : "r"(a[0]), "r"(a[1]), "r"(a[2]), "r"(a[3]), "r"(b[0]), "r"(b[1]));
}

// smem strides (bf16 elements); padded for conflict-free ldmatrix
#define AS 264    // A_s: RPC rows x 256 k
#define BS 136    // B_s: 256 k x 128 n
#define SMEM_A_ELEMS (RPC * AS)
#define SMEM_B_ELEMS (256 * BS)
#define SMEM_BYTES   ((SMEM_A_ELEMS + SMEM_B_ELEMS) * 2 + 512)

// ---------------------------------------------------------------------------
// Tensor-core (mma.sync bf16x3) 4-way projection GEMM.
//   dst[w] = act(A) @ W[w], w=0..3 ; dst[3] += bias
// One CTA = 192 rows, loops over 4 weights. 512 threads (16 warps):
// warp = (rg: 4 row groups x 48 rows) x (cg: 4 col groups x 32 cols).
// ---------------------------------------------------------------------------
__global__ void __launch_bounds__(512, 1) gemm_hmma_kernel(
    const float* __restrict__ A, const __nv_bfloat16* __restrict__ Bsp,
    OutArgs oa, int apply_relu)
{
    extern __shared__ char smem[];
    __nv_bfloat16* A_s = (__nv_bfloat16*)smem;
    __nv_bfloat16* B_s = A_s + SMEM_A_ELEMS;
    float* bias_s = (float*)(B_s + SMEM_B_ELEMS);

    const int t = threadIdx.x;
    const int wid = t >> 5;
    const int ln = t & 31;
    const int rg = wid & 3;        // rows rg*48 .. +47
    const int cg = wid >> 2;       // cols cg*32 .. +31
    const int row0 = blockIdx.x * RPC;

    if (t < 128) bias_s[t] = oa.bias[t];

    // ---- A convert: load f32, optional relu, bf16-split into A_s ----
    #pragma unroll 4
    for (int l = 0; l < 12; l++) {
        int idx = l * 512 + t;
        int r = idx >> 5;
        int c4 = (idx & 31) * 4;
        int grow = row0 + r;
        float4 v = make_float4(0.f, 0.f, 0.f, 0.f);
        if (grow < NN) v = *(const float4*)&A[(size_t)grow * DD + c4];
        if (apply_relu) {
            v.x = fmaxf(v.x, 0.f); v.y = fmaxf(v.y, 0.f);
            v.z = fmaxf(v.z, 0.f); v.w = fmaxf(v.w, 0.f);
        }
        uint2 hi, lo;
        split4(v, hi, lo);
        *(uint2*)&A_s[r * AS + c4]       = hi;
        *(uint2*)&A_s[r * AS + 128 + c4] = lo;
    }

    const uint32_t sbA = smem_u32(A_s);
    const uint32_t sbB = smem_u32(B_s);
    // per-lane ldmatrix base addresses
    const uint32_t a_row = sbA + (uint32_t)(((rg * 48 + (ln & 15)) * AS + (ln >> 4) * 8) * 2);
    const int mat = ln >> 3, rowin = ln & 7;
    const uint32_t b_base = sbB + (uint32_t)(((((mat & 1) * 8 + rowin) * BS)
                                   + cg * 32 + (mat >> 1) * 8) * 2);

    for (int w = 0; w < 4; w++) {
        // ---- Copy split-B for weight w into smem ----
        const __nv_bfloat16* src = Bsp + (size_t)w * 256 * 128;
        #pragma unroll 4
        for (int l = 0; l < 8; l++) {
            int idx = l * 512 + t;          // uint4 index (8 bf16)
            int r = idx >> 4;
            int q = idx & 15;
            *(uint4*)&B_s[r * BS + q * 8] = *(const uint4*)&src[(size_t)r * 128 + q * 8];
        }
        __syncthreads();

        float ac[3][4][4];
        #pragma unroll
        for (int mi = 0; mi < 3; mi++)
            #pragma unroll
            for (int nt = 0; nt < 4; nt++)
                #pragma unroll
                for (int j = 0; j < 4; j++) ac[mi][nt][j] = 0.f;

        // ---- 3 passes: ahi*bhi, alo*bhi, ahi*blo ----
        #pragma unroll
        for (int pass = 0; pass < 3; pass++) {
            const int kbA = (pass == 1) ? 128 : 0;
            const int kbB = (pass == 2) ? 128 : 0;
            #pragma unroll
            for (int ks = 0; ks < 8; ks++) {
                const int kA = kbA + ks * 16;
                const int kB = kbB + ks * 16;
                uint32_t bf[2][4];
                #pragma unroll
                for (int np = 0; np < 2; np++)
                    ldsm4t(bf[np], b_base + (uint32_t)((kB * BS + np * 16) * 2));
                uint32_t af[3][4];
                #pragma unroll
                for (int mi = 0; mi < 3; mi++)
                    ldsm4(af[mi], a_row + (uint32_t)(((mi * 16) * AS + kA) * 2));
                #pragma unroll
                for (int mi = 0; mi < 3; mi++)
                    #pragma unroll
                    for (int np = 0; np < 2; np++) {
                        mma16816(ac[mi][2 * np],     af[mi], &bf[np][0]);
                        mma16816(ac[mi][2 * np + 1], af[mi], &bf[np][2]);
                    }
            }
        }
        __syncthreads();   // all warps done reading B_s before next copy

        // ---- Epilogue: direct fp32 stores; bias on skip path (w==3) ----
        float* dst = oa.dst[w];
        const int r_base = row0 + rg * 48 + (ln >> 2);
        const int c_base = cg * 32 + (ln & 3) * 2;
        const bool add_bias = (w == 3);
        #pragma unroll
        for (int mi = 0; mi < 3; mi++) {
            const int r_m = r_base + mi * 16;
            #pragma unroll
            for (int nt = 0; nt < 4; nt++) {
                const int c = c_base + nt * 8;
                float b0 = 0.f, b1 = 0.f;
                if (add_bias) { b0 = bias_s[c]; b1 = bias_s[c + 1]; }
                if (r_m < NN)
                    *(float2*)&dst[(size_t)r_m * DD + c] =
                        make_float2(ac[mi][nt][0] + b0, ac[mi][nt][1] + b1);
                if (r_m + 8 < NN)
                    *(float2*)&dst[(size_t)(r_m + 8) * DD + c] =
                        make_float2(ac[mi][nt][2] + b0, ac[mi][nt][3] + b1);
            }
        }
    }
}

// ---------------------------------------------------------------------------
// Edge kernel: one warp per edge, lane handles 4 consecutive features.
//   eta = sigmoid(K[tgt] + Q[src]); msg = eta * V[src]; red.v4 into out[tgt]
// ---------------------------------------------------------------------------
__global__ void __launch_bounds__(256) edge_kernel(
    const void* __restrict__ edge_index,
    const float* __restrict__ K, const float* __restrict__ Q,
    const float* __restrict__ V, float* __restrict__ out)
{
    int warp = (blockIdx.x * blockDim.x + threadIdx.x) >> 5;
    if (warp >= NE) return;
    int lane = threadIdx.x & 31;

    int src, tgt;
    if (g_is32) {
        const int* ei = (const int*)edge_index;
        src = ei[warp];
        tgt = ei[NE + warp];
    } else {
        const long long* ei = (const long long*)edge_index;
        src = (int)ei[warp];
        tgt = (int)ei[NE + warp];
    }

    int d0 = lane * 4;
    float4 kt = *(const float4*)&K[(size_t)tgt * DD + d0];
    float4 qs = *(const float4*)&Q[(size_t)src * DD + d0];
    float4 vs = *(const float4*)&V[(size_t)src * DD + d0];

    float4 m;
    m.x = vs.x / (1.f + __expf(-(kt.x + qs.x)));
    m.y = vs.y / (1.f + __expf(-(kt.y + qs.y)));
    m.z = vs.z / (1.f + __expf(-(kt.z + qs.z)));
    m.w = vs.w / (1.f + __expf(-(kt.w + qs.w)));

    float* o = &out[(size_t)tgt * DD + d0];
    asm volatile("red.global.add.v4.f32 [%0], {%1, %2, %3, %4};"
                 :: "l"(o), "f"(m.x), "f"(m.y), "f"(m.z), "f"(m.w)
                 : "memory");
}

// ---------------------------------------------------------------------------
extern "C" void kernel_launch(void* const* d_in, const int* in_sizes, int n_in,
                              void* d_out, int out_size)
{
    const float* x   = (const float*)d_in[0];
    const void*  ei  = d_in[1];
    const float* Wk1 = (const float*)d_in[2];
    const float* Wq1 = (const float*)d_in[3];
    const float* Wv1 = (const float*)d_in[4];
    const float* Ws1 = (const float*)d_in[5];
    const float* b1  = (const float*)d_in[6];
    const float* Wk2 = (const float*)d_in[7];
    const float* Wq2 = (const float*)d_in[8];
    const float* Wv2 = (const float*)d_in[9];
    const float* Ws2 = (const float*)d_in[10];
    const float* b2  = (const float*)d_in[11];
    float* out = (float*)d_out;

    float *pK, *pQ, *pV, *pH;
    __nv_bfloat16* pBs;
    cudaGetSymbolAddress((void**)&pK, g_K);
    cudaGetSymbolAddress((void**)&pQ, g_Q);
    cudaGetSymbolAddress((void**)&pV, g_V);
    cudaGetSymbolAddress((void**)&pH, g_H);
    cudaGetSymbolAddress((void**)&pBs, g_Bs);

    cudaFuncSetAttribute(gemm_hmma_kernel,
                         cudaFuncAttributeMaxDynamicSharedMemorySize, SMEM_BYTES);

    detect_init_kernel<<<1, 1>>>();
    detect_kernel<<<(NE + 255) / 256, 256>>>((const unsigned int*)ei);

    PrepArgs pa;
    pa.W[0] = Wk1; pa.W[1] = Wq1; pa.W[2] = Wv1; pa.W[3] = Ws1;
    pa.W[4] = Wk2; pa.W[5] = Wq2; pa.W[6] = Wv2; pa.W[7] = Ws2;
    prep_weights<<<8, 256>>>(pa);

    dim3 ggrid((NN + RPC - 1) / RPC);
    dim3 egrid((NE * 32 + 255) / 256);

    // ---- Layer 1 ----
    OutArgs o1;
    o1.dst[0] = pK; o1.dst[1] = pQ; o1.dst[2] = pV; o1.dst[3] = pH;
    o1.bias = b1;
    gemm_hmma_kernel<<<ggrid, 512, SMEM_BYTES>>>(x, pBs, o1, /*relu=*/0);
    edge_kernel<<<egrid, 256>>>(ei, pK, pQ, pV, pH);

    // ---- Layer 2 (ReLU fused into A convert) ----
    OutArgs o2;
    o2.dst[0] = pK; o2.dst[1] = pQ; o2.dst[2] = pV; o2.dst[3] = out;
    o2.bias = b2;
    gemm_hmma_kernel<<<ggrid, 512, SMEM_BYTES>>>(pH, pBs + (size_t)4 * 256 * 128, o2, /*relu=*/1);
    edge_kernel<<<egrid, 256>>>(ei, pK, pQ, pV, out);
}

// round 8
// speedup vs baseline: 1.7515x; 1.1636x over previous
#include <cuda_runtime.h>
#include <cuda_bf16.h>
#include <cstdint>
#include <cstddef>

#define NN 50000
#define NE 400000
#define DD 128
#define RPC 192                    // rows per CTA

// Scratch (device globals: allocation-free rule)
__device__ float g_K[NN * DD];
__device__ float g_Q[NN * DD];
__device__ float g_V[NN * DD];
__device__ float g_H[NN * DD];
__device__ __nv_bfloat16 g_Bs[8 * 256 * 128];   // split weights: [w][khi|klo][n]
__device__ int   g_is32;

struct OutArgs {
    float*       dst[4];   // dst[0..2] = K,Q,V ; dst[3] = skip accumulator
    const float* bias;     // added to dst[3]
};
struct PrepArgs { const float* W[8]; };

// ---------------------------------------------------------------------------
// int32-vs-int64 edge_index detection (odd 32-bit words all zero => int64).
// ---------------------------------------------------------------------------
__global__ void detect_init_kernel() { g_is32 = 0; }
__global__ void detect_kernel(const unsigned int* __restrict__ w) {
    int i = blockIdx.x * blockDim.x + threadIdx.x;
    if (i >= NE) return;
    if (w[2 * i + 1] != 0u) atomicOr(&g_is32, 1);
}

// ---------------------------------------------------------------------------
// bf16 split: v = hi + lo (+ O(2^-16 |v|))
// ---------------------------------------------------------------------------
__device__ __forceinline__ void split4(float4 v, uint2& hi, uint2& lo) {
    __nv_bfloat16 hx = __float2bfloat16(v.x);
    __nv_bfloat16 hy = __float2bfloat16(v.y);
    __nv_bfloat16 hz = __float2bfloat16(v.z);
    __nv_bfloat16 hw = __float2bfloat16(v.w);
    __nv_bfloat16 lx = __float2bfloat16(v.x - __bfloat162float(hx));
    __nv_bfloat16 ly = __float2bfloat16(v.y - __bfloat162float(hy));
    __nv_bfloat16 lz = __float2bfloat16(v.z - __bfloat162float(hz));
    __nv_bfloat16 lw = __float2bfloat16(v.w - __bfloat162float(hw));
    hi.x = (uint32_t)__bfloat16_as_ushort(hx) | ((uint32_t)__bfloat16_as_ushort(hy) << 16);
    hi.y = (uint32_t)__bfloat16_as_ushort(hz) | ((uint32_t)__bfloat16_as_ushort(hw) << 16);
    lo.x = (uint32_t)__bfloat16_as_ushort(lx) | ((uint32_t)__bfloat16_as_ushort(ly) << 16);
    lo.y = (uint32_t)__bfloat16_as_ushort(lz) | ((uint32_t)__bfloat16_as_ushort(lw) << 16);
}

// ---------------------------------------------------------------------------
// Weight prep: split each W[k][n] (f32) into g_Bs[w]: rows 0..127 = bf16 hi(k),
// rows 128..255 = bf16 lo(k), n contiguous.
// ---------------------------------------------------------------------------
__global__ void __launch_bounds__(256) prep_weights(PrepArgs pa) {
    const int w = blockIdx.x;
    const float* __restrict__ W = pa.W[w];
    __nv_bfloat16* __restrict__ out = g_Bs + (size_t)w * 256 * 128;
    const int t = threadIdx.x;
    #pragma unroll 4
    for (int l = 0; l < 16; l++) {
        int idx = l * 256 + t;
        int k = idx >> 5;
        int c4 = (idx & 31) * 4;
        float4 v = *(const float4*)&W[(size_t)k * DD + c4];
        uint2 hi, lo;
        split4(v, hi, lo);
        *(uint2*)&out[(size_t)k * 128 + c4]         = hi;
        *(uint2*)&out[(size_t)(128 + k) * 128 + c4] = lo;
    }
}

// ---------------------------------------------------------------------------
// HMMA helpers
// ---------------------------------------------------------------------------
__device__ __forceinline__ uint32_t smem_u32(const void* p) {
    uint32_t a;
    asm("{ .reg .u64 t; cvta.to.shared.u64 t, %1; cvt.u32.u64 %0, t; }"
        : "=r"(a) : "l"(p));
    return a;
}

__device__ __forceinline__ void ldsm4(uint32_t* r, uint32_t addr) {
    asm volatile("ldmatrix.sync.aligned.m8n8.x4.shared.b16 {%0,%1,%2,%3}, [%4];"
        : "=r"(r[0]), "=r"(r[1]), "=r"(r[2]), "=r"(r[3]) : "r"(addr));
}
__device__ __forceinline__ void ldsm4t(uint32_t* r, uint32_t addr) {
    asm volatile("ldmatrix.sync.aligned.m8n8.x4.trans.shared.b16 {%0,%1,%2,%3}, [%4];"
        : "=r"(r[0]), "=r"(r[1]), "=r"(r[2]), "=r"(r[3]) : "r"(addr));
}
__device__ __forceinline__ void mma16816(float* d, const uint32_t* a, const uint32_t* b) {
    asm volatile(
        "mma.sync.aligned.m16n8k16.row.col.f32.bf16.bf16.f32 "
        "{%0,%1,%2,%3}, {%4,%5,%6,%7}, {%8,%9}, {%0,%1,%2,%3};"
        : "+f"(d[0]), "+f"(d[1]), "+f"(d[2]), "+f"(d[3])
        : "r"(a[0]), "r"(a[1]), "r"(a[2]), "r"(a[3]), "r"(b[0]), "r"(b[1]));
}

// smem strides (bf16 elements); padded for conflict-free ldmatrix
#define AS 264    // A_s: RPC rows x 256 k
#define BS 136    // B_s: 256 k x 128 n
#define SMEM_A_ELEMS (RPC * AS)
#define SMEM_B_ELEMS (256 * BS)
#define SMEM_BYTES   ((SMEM_A_ELEMS + SMEM_B_ELEMS) * 2 + 512)

// ---------------------------------------------------------------------------
// Tensor-core (mma.sync bf16x3 split, MERGED single k-loop) 4-way GEMM.
//   dst[w] = act(A) @ W[w], w=0..3 ; dst[3] += bias
// One CTA = 192 rows, loops over 4 weights. 512 threads (16 warps):
// warp = (rg: 4 row groups x 48 rows) x (cg: 4 col groups x 32 cols).
// Per k-step: 10 ldsm.x4 (ahi x3, alo x3, bhi x2, blo x2) then 36 mma
// (ahi*bhi + alo*bhi + ahi*blo) into 12 independent accumulator groups.
// ---------------------------------------------------------------------------
__global__ void __launch_bounds__(512, 1) gemm_hmma_kernel(
    const float* __restrict__ A, const __nv_bfloat16* __restrict__ Bsp,
    OutArgs oa, int apply_relu)
{
    extern __shared__ char smem[];
    __nv_bfloat16* A_s = (__nv_bfloat16*)smem;
    __nv_bfloat16* B_s = A_s + SMEM_A_ELEMS;
    float* bias_s = (float*)(B_s + SMEM_B_ELEMS);

    const int t = threadIdx.x;
    const int wid = t >> 5;
    const int ln = t & 31;
    const int rg = wid & 3;        // rows rg*48 .. +47
    const int cg = wid >> 2;       // cols cg*32 .. +31
    const int row0 = blockIdx.x * RPC;

    if (t < 128) bias_s[t] = oa.bias[t];

    // ---- A convert: load f32, optional relu, bf16-split into A_s ----
    #pragma unroll 4
    for (int l = 0; l < 12; l++) {
        int idx = l * 512 + t;
        int r = idx >> 5;
        int c4 = (idx & 31) * 4;
        int grow = row0 + r;
        float4 v = make_float4(0.f, 0.f, 0.f, 0.f);
        if (grow < NN) v = *(const float4*)&A[(size_t)grow * DD + c4];
        if (apply_relu) {
            v.x = fmaxf(v.x, 0.f); v.y = fmaxf(v.y, 0.f);
            v.z = fmaxf(v.z, 0.f); v.w = fmaxf(v.w, 0.f);
        }
        uint2 hi, lo;
        split4(v, hi, lo);
        *(uint2*)&A_s[r * AS + c4]       = hi;
        *(uint2*)&A_s[r * AS + 128 + c4] = lo;
    }

    const uint32_t sbA = smem_u32(A_s);
    const uint32_t sbB = smem_u32(B_s);
    // per-lane ldmatrix base addresses
    const uint32_t a_row = sbA + (uint32_t)(((rg * 48 + (ln & 15)) * AS + (ln >> 4) * 8) * 2);
    const int mat = ln >> 3, rowin = ln & 7;
    const uint32_t b_base = sbB + (uint32_t)(((((mat & 1) * 8 + rowin) * BS)
                                   + cg * 32 + (mat >> 1) * 8) * 2);

    for (int w = 0; w < 4; w++) {
        // ---- Copy split-B for weight w into smem ----
        const __nv_bfloat16* src = Bsp + (size_t)w * 256 * 128;
        #pragma unroll 4
        for (int l = 0; l < 8; l++) {
            int idx = l * 512 + t;          // uint4 index (8 bf16)
            int r = idx >> 4;
            int q = idx & 15;
            *(uint4*)&B_s[r * BS + q * 8] = *(const uint4*)&src[(size_t)r * 128 + q * 8];
        }
        __syncthreads();

        float ac[3][4][4];
        #pragma unroll
        for (int mi = 0; mi < 3; mi++)
            #pragma unroll
            for (int nt = 0; nt < 4; nt++)
                #pragma unroll
                for (int j = 0; j < 4; j++) ac[mi][nt][j] = 0.f;

        // ---- Merged k-loop: all 3 split-products per k-step ----
        #pragma unroll
        for (int ks = 0; ks < 8; ks++) {
            const int kA = ks * 16;
            uint32_t ahi[3][4], alo[3][4], bhi[2][4], blo[2][4];
            #pragma unroll
            for (int np = 0; np < 2; np++)
                ldsm4t(bhi[np], b_base + (uint32_t)((kA * BS + np * 16) * 2));
            #pragma unroll
            for (int np = 0; np < 2; np++)
                ldsm4t(blo[np], b_base + (uint32_t)(((128 + kA) * BS + np * 16) * 2));
            #pragma unroll
            for (int mi = 0; mi < 3; mi++)
                ldsm4(ahi[mi], a_row + (uint32_t)(((mi * 16) * AS + kA) * 2));
            #pragma unroll
            for (int mi = 0; mi < 3; mi++)
                ldsm4(alo[mi], a_row + (uint32_t)(((mi * 16) * AS + 128 + kA) * 2));

            #pragma unroll
            for (int mi = 0; mi < 3; mi++)
                #pragma unroll
                for (int np = 0; np < 2; np++) {
                    mma16816(ac[mi][2 * np],     ahi[mi], &bhi[np][0]);
                    mma16816(ac[mi][2 * np + 1], ahi[mi], &bhi[np][2]);
                    mma16816(ac[mi][2 * np],     alo[mi], &bhi[np][0]);
                    mma16816(ac[mi][2 * np + 1], alo[mi], &bhi[np][2]);
                    mma16816(ac[mi][2 * np],     ahi[mi], &blo[np][0]);
                    mma16816(ac[mi][2 * np + 1], ahi[mi], &blo[np][2]);
                }
        }
        __syncthreads();   // all warps done reading B_s before next copy

        // ---- Epilogue: direct fp32 stores; bias on skip path (w==3) ----
        float* dst = oa.dst[w];
        const int r_base = row0 + rg * 48 + (ln >> 2);
        const int c_base = cg * 32 + (ln & 3) * 2;
        const bool add_bias = (w == 3);
        #pragma unroll
        for (int mi = 0; mi < 3; mi++) {
            const int r_m = r_base + mi * 16;
            #pragma unroll
            for (int nt = 0; nt < 4; nt++) {
                const int c = c_base + nt * 8;
                float b0 = 0.f, b1 = 0.f;
                if (add_bias) { b0 = bias_s[c]; b1 = bias_s[c + 1]; }
                if (r_m < NN)
                    *(float2*)&dst[(size_t)r_m * DD + c] =
                        make_float2(ac[mi][nt][0] + b0, ac[mi][nt][1] + b1);
                if (r_m + 8 < NN)
                    *(float2*)&dst[(size_t)(r_m + 8) * DD + c] =
                        make_float2(ac[mi][nt][2] + b0, ac[mi][nt][3] + b1);
            }
        }
    }
}

// ---------------------------------------------------------------------------
// Edge kernel: one warp per edge, lane handles 4 consecutive features.
//   eta = sigmoid(K[tgt] + Q[src]); msg = eta * V[src]; red.v4 into out[tgt]
// ---------------------------------------------------------------------------
__global__ void __launch_bounds__(256) edge_kernel(
    const void* __restrict__ edge_index,
    const float* __restrict__ K, const float* __restrict__ Q,
    const float* __restrict__ V, float* __restrict__ out)
{
    int warp = (blockIdx.x * blockDim.x + threadIdx.x) >> 5;
    if (warp >= NE) return;
    int lane = threadIdx.x & 31;

    int src, tgt;
    if (g_is32) {
        const int* ei = (const int*)edge_index;
        src = ei[warp];
        tgt = ei[NE + warp];
    } else {
        const long long* ei = (const long long*)edge_index;
        src = (int)ei[warp];
        tgt = (int)ei[NE + warp];
    }

    int d0 = lane * 4;
    float4 kt = *(const float4*)&K[(size_t)tgt * DD + d0];
    float4 qs = *(const float4*)&Q[(size_t)src * DD + d0];
    float4 vs = *(const float4*)&V[(size_t)src * DD + d0];

    float4 m;
    m.x = vs.x / (1.f + __expf(-(kt.x + qs.x)));
    m.y = vs.y / (1.f + __expf(-(kt.y + qs.y)));
    m.z = vs.z / (1.f + __expf(-(kt.z + qs.z)));
    m.w = vs.w / (1.f + __expf(-(kt.w + qs.w)));

    float* o = &out[(size_t)tgt * DD + d0];
    asm volatile("red.global.add.v4.f32 [%0], {%1, %2, %3, %4};"
                 :: "l"(o), "f"(m.x), "f"(m.y), "f"(m.z), "f"(m.w)
                 : "memory");
}

// ---------------------------------------------------------------------------
extern "C" void kernel_launch(void* const* d_in, const int* in_sizes, int n_in,
                              void* d_out, int out_size)
{
    const float* x   = (const float*)d_in[0];
    const void*  ei  = d_in[1];
    const float* Wk1 = (const float*)d_in[2];
    const float* Wq1 = (const float*)d_in[3];
    const float* Wv1 = (const float*)d_in[4];
    const float* Ws1 = (const float*)d_in[5];
    const float* b1  = (const float*)d_in[6];
    const float* Wk2 = (const float*)d_in[7];
    const float* Wq2 = (const float*)d_in[8];
    const float* Wv2 = (const float*)d_in[9];
    const float* Ws2 = (const float*)d_in[10];
    const float* b2  = (const float*)d_in[11];
    float* out = (float*)d_out;

    float *pK, *pQ, *pV, *pH;
    __nv_bfloat16* pBs;
    cudaGetSymbolAddress((void**)&pK, g_K);
    cudaGetSymbolAddress((void**)&pQ, g_Q);
    cudaGetSymbolAddress((void**)&pV, g_V);
    cudaGetSymbolAddress((void**)&pH, g_H);
    cudaGetSymbolAddress((void**)&pBs, g_Bs);

    cudaFuncSetAttribute(gemm_hmma_kernel,
                         cudaFuncAttributeMaxDynamicSharedMemorySize, SMEM_BYTES);

    detect_init_kernel<<<1, 1>>>();
    detect_kernel<<<(NE + 255) / 256, 256>>>((const unsigned int*)ei);

    PrepArgs pa;
    pa.W[0] = Wk1; pa.W[1] = Wq1; pa.W[2] = Wv1; pa.W[3] = Ws1;
    pa.W[4] = Wk2; pa.W[5] = Wq2; pa.W[6] = Wv2; pa.W[7] = Ws2;
    prep_weights<<<8, 256>>>(pa);

    dim3 ggrid((NN + RPC - 1) / RPC);
    dim3 egrid((NE * 32 + 255) / 256);

    // ---- Layer 1 ----
    OutArgs o1;
    o1.dst[0] = pK; o1.dst[1] = pQ; o1.dst[2] = pV; o1.dst[3] = pH;
    o1.bias = b1;
    gemm_hmma_kernel<<<ggrid, 512, SMEM_BYTES>>>(x, pBs, o1, /*relu=*/0);
    edge_kernel<<<egrid, 256>>>(ei, pK, pQ, pV, pH);

    // ---- Layer 2 (ReLU fused into A convert) ----
    OutArgs o2;
    o2.dst[0] = pK; o2.dst[1] = pQ; o2.dst[2] = pV; o2.dst[3] = out;
    o2.bias = b2;
    gemm_hmma_kernel<<<ggrid, 512, SMEM_BYTES>>>(pH, pBs + (size_t)4 * 256 * 128, o2, /*relu=*/1);
    edge_kernel<<<egrid, 256>>>(ei, pK, pQ, pV, out);
}

// round 9
// speedup vs baseline: 1.8884x; 1.0782x over previous
#include <cuda_runtime.h>
#include <cuda_bf16.h>
#include <cstdint>
#include <cstddef>

#define NN 50000
#define NE 400000
#define DD 128
#define RPC 192                    // rows per CTA
#define NT_G 768                   // gemm threads (24 warps)

// Scratch (device globals: allocation-free rule)
__device__ float g_K[NN * DD];
__device__ float g_Q[NN * DD];
__device__ float g_V[NN * DD];
__device__ float g_H[NN * DD];
__device__ __nv_bfloat16 g_Bs[8 * 256 * 128];   // split weights: [w][khi|klo][n]
__device__ int   g_is32;

struct OutArgs {
    float*       dst[4];   // dst[0..2] = K,Q,V ; dst[3] = skip accumulator
    const float* bias;     // added to dst[3]
};
struct PrepArgs { const float* W[8]; };

// ---------------------------------------------------------------------------
// int32-vs-int64 edge_index detection (odd 32-bit words all zero => int64).
// ---------------------------------------------------------------------------
__global__ void detect_init_kernel() { g_is32 = 0; }
__global__ void detect_kernel(const unsigned int* __restrict__ w) {
    int i = blockIdx.x * blockDim.x + threadIdx.x;
    if (i >= NE) return;
    if (w[2 * i + 1] != 0u) atomicOr(&g_is32, 1);
}

// ---------------------------------------------------------------------------
// bf16 split: v = hi + lo (+ O(2^-16 |v|))
// ---------------------------------------------------------------------------
__device__ __forceinline__ void split4(float4 v, uint2& hi, uint2& lo) {
    __nv_bfloat16 hx = __float2bfloat16(v.x);
    __nv_bfloat16 hy = __float2bfloat16(v.y);
    __nv_bfloat16 hz = __float2bfloat16(v.z);
    __nv_bfloat16 hw = __float2bfloat16(v.w);
    __nv_bfloat16 lx = __float2bfloat16(v.x - __bfloat162float(hx));
    __nv_bfloat16 ly = __float2bfloat16(v.y - __bfloat162float(hy));
    __nv_bfloat16 lz = __float2bfloat16(v.z - __bfloat162float(hz));
    __nv_bfloat16 lw = __float2bfloat16(v.w - __bfloat162float(hw));
    hi.x = (uint32_t)__bfloat16_as_ushort(hx) | ((uint32_t)__bfloat16_as_ushort(hy) << 16);
    hi.y = (uint32_t)__bfloat16_as_ushort(hz) | ((uint32_t)__bfloat16_as_ushort(hw) << 16);
    lo.x = (uint32_t)__bfloat16_as_ushort(lx) | ((uint32_t)__bfloat16_as_ushort(ly) << 16);
    lo.y = (uint32_t)__bfloat16_as_ushort(lz) | ((uint32_t)__bfloat16_as_ushort(lw) << 16);
}

// ---------------------------------------------------------------------------
// Weight prep: split each W[k][n] (f32) into g_Bs[w]: rows 0..127 = bf16 hi(k),
// rows 128..255 = bf16 lo(k), n contiguous.
// ---------------------------------------------------------------------------
__global__ void __launch_bounds__(256) prep_weights(PrepArgs pa) {
    const int w = blockIdx.x;
    const float* __restrict__ W = pa.W[w];
    __nv_bfloat16* __restrict__ out = g_Bs + (size_t)w * 256 * 128;
    const int t = threadIdx.x;
    #pragma unroll 4
    for (int l = 0; l < 16; l++) {
        int idx = l * 256 + t;
        int k = idx >> 5;
        int c4 = (idx & 31) * 4;
        float4 v = *(const float4*)&W[(size_t)k * DD + c4];
        uint2 hi, lo;
        split4(v, hi, lo);
        *(uint2*)&out[(size_t)k * 128 + c4]         = hi;
        *(uint2*)&out[(size_t)(128 + k) * 128 + c4] = lo;
    }
}

// ---------------------------------------------------------------------------
// HMMA helpers
// ---------------------------------------------------------------------------
__device__ __forceinline__ uint32_t smem_u32(const void* p) {
    uint32_t a;
    asm("{ .reg .u64 t; cvta.to.shared.u64 t, %1; cvt.u32.u64 %0, t; }"
        : "=r"(a) : "l"(p));
    return a;
}

__device__ __forceinline__ void ldsm4(uint32_t* r, uint32_t addr) {
    asm volatile("ldmatrix.sync.aligned.m8n8.x4.shared.b16 {%0,%1,%2,%3}, [%4];"
        : "=r"(r[0]), "=r"(r[1]), "=r"(r[2]), "=r"(r[3]) : "r"(addr));
}
__device__ __forceinline__ void ldsm4t(uint32_t* r, uint32_t addr) {
    asm volatile("ldmatrix.sync.aligned.m8n8.x4.trans.shared.b16 {%0,%1,%2,%3}, [%4];"
        : "=r"(r[0]), "=r"(r[1]), "=r"(r[2]), "=r"(r[3]) : "r"(addr));
}
__device__ __forceinline__ void mma16816(float* d, const uint32_t* a, const uint32_t* b) {
    asm volatile(
        "mma.sync.aligned.m16n8k16.row.col.f32.bf16.bf16.f32 "
        "{%0,%1,%2,%3}, {%4,%5,%6,%7}, {%8,%9}, {%0,%1,%2,%3};"
        : "+f"(d[0]), "+f"(d[1]), "+f"(d[2]), "+f"(d[3])
        : "r"(a[0]), "r"(a[1]), "r"(a[2]), "r"(a[3]), "r"(b[0]), "r"(b[1]));
}

// smem strides (bf16 elements); padded for conflict-free ldmatrix
#define AS 264    // A_s: RPC rows x 256 k
#define BS 136    // B_s: 256 k x 128 n
#define SMEM_A_ELEMS (RPC * AS)
#define SMEM_B_ELEMS (256 * BS)
#define SMEM_BYTES   ((SMEM_A_ELEMS + SMEM_B_ELEMS) * 2 + 512)

// ---------------------------------------------------------------------------
// Tensor-core (mma.sync bf16x3 split, merged k-loop) 4-way GEMM.
//   dst[w] = act(A) @ W[w], w=0..3 ; dst[3] += bias
// One CTA = 192 rows. 768 threads (24 warps): warp = (rg: 6 row groups x 32
// rows) x (cg: 4 col groups x 32 cols). Per k-step: 8 ldsm.x4 then 24 mma.
// ---------------------------------------------------------------------------
__global__ void __launch_bounds__(NT_G, 1) gemm_hmma_kernel(
    const float* __restrict__ A, const __nv_bfloat16* __restrict__ Bsp,
    OutArgs oa, int apply_relu)
{
    extern __shared__ char smem[];
    __nv_bfloat16* A_s = (__nv_bfloat16*)smem;
    __nv_bfloat16* B_s = A_s + SMEM_A_ELEMS;
    float* bias_s = (float*)(B_s + SMEM_B_ELEMS);

    const int t = threadIdx.x;
    const int wid = t >> 5;
    const int ln = t & 31;
    const int rg = wid % 6;        // rows rg*32 .. +31
    const int cg = wid / 6;        // cols cg*32 .. +31
    const int row0 = blockIdx.x * RPC;

    if (t < 128) bias_s[t] = oa.bias[t];

    // ---- A convert: load f32, optional relu, bf16-split into A_s ----
    #pragma unroll 4
    for (int l = 0; l < 8; l++) {
        int idx = l * NT_G + t;              // 6144 float4 tasks
        int r = idx >> 5;
        int c4 = (idx & 31) * 4;
        int grow = row0 + r;
        float4 v = make_float4(0.f, 0.f, 0.f, 0.f);
        if (grow < NN) v = *(const float4*)&A[(size_t)grow * DD + c4];
        if (apply_relu) {
            v.x = fmaxf(v.x, 0.f); v.y = fmaxf(v.y, 0.f);
            v.z = fmaxf(v.z, 0.f); v.w = fmaxf(v.w, 0.f);
        }
        uint2 hi, lo;
        split4(v, hi, lo);
        *(uint2*)&A_s[r * AS + c4]       = hi;
        *(uint2*)&A_s[r * AS + 128 + c4] = lo;
    }

    const uint32_t sbA = smem_u32(A_s);
    const uint32_t sbB = smem_u32(B_s);
    // per-lane ldmatrix base addresses
    const uint32_t a_row = sbA + (uint32_t)(((rg * 32 + (ln & 15)) * AS + (ln >> 4) * 8) * 2);
    const int mat = ln >> 3, rowin = ln & 7;
    const uint32_t b_base = sbB + (uint32_t)(((((mat & 1) * 8 + rowin) * BS)
                                   + cg * 32 + (mat >> 1) * 8) * 2);

    for (int w = 0; w < 4; w++) {
        // ---- Copy split-B for weight w into smem (4096 uint4 tasks) ----
        const __nv_bfloat16* src = Bsp + (size_t)w * 256 * 128;
        #pragma unroll
        for (int l = 0; l < 6; l++) {
            int idx = l * NT_G + t;
            if (idx < 4096) {
                int r = idx >> 4;
                int q = idx & 15;
                *(uint4*)&B_s[r * BS + q * 8] = *(const uint4*)&src[(size_t)r * 128 + q * 8];
            }
        }
        __syncthreads();

        float ac[2][4][4];
        #pragma unroll
        for (int mi = 0; mi < 2; mi++)
            #pragma unroll
            for (int nt = 0; nt < 4; nt++)
                #pragma unroll
                for (int j = 0; j < 4; j++) ac[mi][nt][j] = 0.f;

        // ---- Merged k-loop: all 3 split-products per k-step ----
        #pragma unroll
        for (int ks = 0; ks < 8; ks++) {
            const int kA = ks * 16;
            uint32_t ahi[2][4], alo[2][4], bhi[2][4], blo[2][4];
            #pragma unroll
            for (int np = 0; np < 2; np++)
                ldsm4t(bhi[np], b_base + (uint32_t)((kA * BS + np * 16) * 2));
            #pragma unroll
            for (int np = 0; np < 2; np++)
                ldsm4t(blo[np], b_base + (uint32_t)(((128 + kA) * BS + np * 16) * 2));
            #pragma unroll
            for (int mi = 0; mi < 2; mi++)
                ldsm4(ahi[mi], a_row + (uint32_t)(((mi * 16) * AS + kA) * 2));
            #pragma unroll
            for (int mi = 0; mi < 2; mi++)
                ldsm4(alo[mi], a_row + (uint32_t)(((mi * 16) * AS + 128 + kA) * 2));

            #pragma unroll
            for (int mi = 0; mi < 2; mi++)
                #pragma unroll
                for (int np = 0; np < 2; np++) {
                    mma16816(ac[mi][2 * np],     ahi[mi], &bhi[np][0]);
                    mma16816(ac[mi][2 * np + 1], ahi[mi], &bhi[np][2]);
                    mma16816(ac[mi][2 * np],     alo[mi], &bhi[np][0]);
                    mma16816(ac[mi][2 * np + 1], alo[mi], &bhi[np][2]);
                    mma16816(ac[mi][2 * np],     ahi[mi], &blo[np][0]);
                    mma16816(ac[mi][2 * np + 1], ahi[mi], &blo[np][2]);
                }
        }
        __syncthreads();   // all warps done reading B_s before next copy

        // ---- Epilogue: direct fp32 stores; bias on skip path (w==3) ----
        float* dst = oa.dst[w];
        const int r_base = row0 + rg * 32 + (ln >> 2);
        const int c_base = cg * 32 + (ln & 3) * 2;
        const bool add_bias = (w == 3);
        #pragma unroll
        for (int mi = 0; mi < 2; mi++) {
            const int r_m = r_base + mi * 16;
            #pragma unroll
            for (int nt = 0; nt < 4; nt++) {
                const int c = c_base + nt * 8;
                float b0 = 0.f, b1 = 0.f;
                if (add_bias) { b0 = bias_s[c]; b1 = bias_s[c + 1]; }
                if (r_m < NN)
                    *(float2*)&dst[(size_t)r_m * DD + c] =
                        make_float2(ac[mi][nt][0] + b0, ac[mi][nt][1] + b1);
                if (r_m + 8 < NN)
                    *(float2*)&dst[(size_t)(r_m + 8) * DD + c] =
                        make_float2(ac[mi][nt][2] + b0, ac[mi][nt][3] + b1);
            }
        }
    }
}

// ---------------------------------------------------------------------------
// Edge kernel: one warp per TWO edges (batched gathers for 2x MLP).
//   eta = sigmoid(K[tgt] + Q[src]); msg = eta * V[src]; red.v4 into out[tgt]
// ---------------------------------------------------------------------------
__global__ void __launch_bounds__(256) edge_kernel(
    const void* __restrict__ edge_index,
    const float* __restrict__ K, const float* __restrict__ Q,
    const float* __restrict__ V, float* __restrict__ out)
{
    int warp = (blockIdx.x * blockDim.x + threadIdx.x) >> 5;
    int e0 = warp * 2;
    if (e0 >= NE) return;
    int lane = threadIdx.x & 31;
    int d0 = lane * 4;

    int src0, tgt0, src1, tgt1;
    if (g_is32) {
        const int* ei = (const int*)edge_index;
        src0 = ei[e0];     src1 = ei[e0 + 1];
        tgt0 = ei[NE + e0]; tgt1 = ei[NE + e0 + 1];
    } else {
        const long long* ei = (const long long*)edge_index;
        src0 = (int)ei[e0];     src1 = (int)ei[e0 + 1];
        tgt0 = (int)ei[NE + e0]; tgt1 = (int)ei[NE + e0 + 1];
    }

    // issue all 6 gathers before any compute
    float4 kt0 = *(const float4*)&K[(size_t)tgt0 * DD + d0];
    float4 qs0 = *(const float4*)&Q[(size_t)src0 * DD + d0];
    float4 vs0 = *(const float4*)&V[(size_t)src0 * DD + d0];
    float4 kt1 = *(const float4*)&K[(size_t)tgt1 * DD + d0];
    float4 qs1 = *(const float4*)&Q[(size_t)src1 * DD + d0];
    float4 vs1 = *(const float4*)&V[(size_t)src1 * DD + d0];

    float4 m0, m1;
    m0.x = vs0.x / (1.f + __expf(-(kt0.x + qs0.x)));
    m0.y = vs0.y / (1.f + __expf(-(kt0.y + qs0.y)));
    m0.z = vs0.z / (1.f + __expf(-(kt0.z + qs0.z)));
    m0.w = vs0.w / (1.f + __expf(-(kt0.w + qs0.w)));
    m1.x = vs1.x / (1.f + __expf(-(kt1.x + qs1.x)));
    m1.y = vs1.y / (1.f + __expf(-(kt1.y + qs1.y)));
    m1.z = vs1.z / (1.f + __expf(-(kt1.z + qs1.z)));
    m1.w = vs1.w / (1.f + __expf(-(kt1.w + qs1.w)));

    float* o0 = &out[(size_t)tgt0 * DD + d0];
    asm volatile("red.global.add.v4.f32 [%0], {%1, %2, %3, %4};"
                 :: "l"(o0), "f"(m0.x), "f"(m0.y), "f"(m0.z), "f"(m0.w)
                 : "memory");
    float* o1 = &out[(size_t)tgt1 * DD + d0];
    asm volatile("red.global.add.v4.f32 [%0], {%1, %2, %3, %4};"
                 :: "l"(o1), "f"(m1.x), "f"(m1.y), "f"(m1.z), "f"(m1.w)
                 : "memory");
}

// ---------------------------------------------------------------------------
extern "C" void kernel_launch(void* const* d_in, const int* in_sizes, int n_in,
                              void* d_out, int out_size)
{
    const float* x   = (const float*)d_in[0];
    const void*  ei  = d_in[1];
    const float* Wk1 = (const float*)d_in[2];
    const float* Wq1 = (const float*)d_in[3];
    const float* Wv1 = (const float*)d_in[4];
    const float* Ws1 = (const float*)d_in[5];
    const float* b1  = (const float*)d_in[6];
    const float* Wk2 = (const float*)d_in[7];
    const float* Wq2 = (const float*)d_in[8];
    const float* Wv2 = (const float*)d_in[9];
    const float* Ws2 = (const float*)d_in[10];
    const float* b2  = (const float*)d_in[11];
    float* out = (float*)d_out;

    float *pK, *pQ, *pV, *pH;
    __nv_bfloat16* pBs;
    cudaGetSymbolAddress((void**)&pK, g_K);
    cudaGetSymbolAddress((void**)&pQ, g_Q);
    cudaGetSymbolAddress((void**)&pV, g_V);
    cudaGetSymbolAddress((void**)&pH, g_H);
    cudaGetSymbolAddress((void**)&pBs, g_Bs);

    cudaFuncSetAttribute(gemm_hmma_kernel,
                         cudaFuncAttributeMaxDynamicSharedMemorySize, SMEM_BYTES);

    detect_init_kernel<<<1, 1>>>();
    detect_kernel<<<(NE + 255) / 256, 256>>>((const unsigned int*)ei);

    PrepArgs pa;
    pa.W[0] = Wk1; pa.W[1] = Wq1; pa.W[2] = Wv1; pa.W[3] = Ws1;
    pa.W[4] = Wk2; pa.W[5] = Wq2; pa.W[6] = Wv2; pa.W[7] = Ws2;
    prep_weights<<<8, 256>>>(pa);

    dim3 ggrid((NN + RPC - 1) / RPC);
    dim3 egrid((NE / 2 * 32 + 255) / 256);   // one warp per 2 edges

    // ---- Layer 1 ----
    OutArgs o1;
    o1.dst[0] = pK; o1.dst[1] = pQ; o1.dst[2] = pV; o1.dst[3] = pH;
    o1.bias = b1;
    gemm_hmma_kernel<<<ggrid, NT_G, SMEM_BYTES>>>(x, pBs, o1, /*relu=*/0);
    edge_kernel<<<egrid, 256>>>(ei, pK, pQ, pV, pH);

    // ---- Layer 2 (ReLU fused into A convert) ----
    OutArgs o2;
    o2.dst[0] = pK; o2.dst[1] = pQ; o2.dst[2] = pV; o2.dst[3] = out;
    o2.bias = b2;
    gemm_hmma_kernel<<<ggrid, NT_G, SMEM_BYTES>>>(pH, pBs + (size_t)4 * 256 * 128, o2, /*relu=*/1);
    edge_kernel<<<egrid, 256>>>(ei, pK, pQ, pV, out);
}

// round 10
// speedup vs baseline: 1.9779x; 1.0474x over previous
#include <cuda_runtime.h>
#include <cuda_bf16.h>
#include <cstdint>
#include <cstddef>

#define NN 50000
#define NE 400000
#define DD 128
#define RPC 384                    // rows per CTA (2 chunks of 192)
#define CHUNK 192
#define NT_G 768                   // gemm threads (24 warps)

// Scratch (device globals: allocation-free rule)
__device__ float g_K[NN * DD];
__device__ float g_Q[NN * DD];
__device__ float g_V[NN * DD];
__device__ float g_H[NN * DD];
__device__ __nv_bfloat16 g_Bs[8 * 256 * 128];   // split weights: [w][khi|klo][n]
__device__ int   g_is32;

struct OutArgs {
    float*       dst[4];   // dst[0..2] = K,Q,V ; dst[3] = skip accumulator
    const float* bias;     // added to dst[3]
};
struct PrepArgs { const float* W[8]; };

// ---------------------------------------------------------------------------
// int32-vs-int64 edge_index detection (odd 32-bit words all zero => int64).
// ---------------------------------------------------------------------------
__global__ void detect_init_kernel() { g_is32 = 0; }
__global__ void detect_kernel(const unsigned int* __restrict__ w) {
    int i = blockIdx.x * blockDim.x + threadIdx.x;
    if (i >= NE) return;
    if (w[2 * i + 1] != 0u) atomicOr(&g_is32, 1);
}

// ---------------------------------------------------------------------------
// bf16 split: v = hi + lo (+ O(2^-16 |v|))
// ---------------------------------------------------------------------------
__device__ __forceinline__ void split4(float4 v, uint2& hi, uint2& lo) {
    __nv_bfloat16 hx = __float2bfloat16(v.x);
    __nv_bfloat16 hy = __float2bfloat16(v.y);
    __nv_bfloat16 hz = __float2bfloat16(v.z);
    __nv_bfloat16 hw = __float2bfloat16(v.w);
    __nv_bfloat16 lx = __float2bfloat16(v.x - __bfloat162float(hx));
    __nv_bfloat16 ly = __float2bfloat16(v.y - __bfloat162float(hy));
    __nv_bfloat16 lz = __float2bfloat16(v.z - __bfloat162float(hz));
    __nv_bfloat16 lw = __float2bfloat16(v.w - __bfloat162float(hw));
    hi.x = (uint32_t)__bfloat16_as_ushort(hx) | ((uint32_t)__bfloat16_as_ushort(hy) << 16);
    hi.y = (uint32_t)__bfloat16_as_ushort(hz) | ((uint32_t)__bfloat16_as_ushort(hw) << 16);
    lo.x = (uint32_t)__bfloat16_as_ushort(lx) | ((uint32_t)__bfloat16_as_ushort(ly) << 16);
    lo.y = (uint32_t)__bfloat16_as_ushort(lz) | ((uint32_t)__bfloat16_as_ushort(lw) << 16);
}

// ---------------------------------------------------------------------------
// Weight prep: split each W[k][n] (f32) into g_Bs[w]: rows 0..127 = bf16 hi(k),
// rows 128..255 = bf16 lo(k), n contiguous.
// ---------------------------------------------------------------------------
__global__ void __launch_bounds__(256) prep_weights(PrepArgs pa) {
    const int w = blockIdx.x;
    const float* __restrict__ W = pa.W[w];
    __nv_bfloat16* __restrict__ out = g_Bs + (size_t)w * 256 * 128;
    const int t = threadIdx.x;
    #pragma unroll 4
    for (int l = 0; l < 16; l++) {
        int idx = l * 256 + t;
        int k = idx >> 5;
        int c4 = (idx & 31) * 4;
        float4 v = *(const float4*)&W[(size_t)k * DD + c4];
        uint2 hi, lo;
        split4(v, hi, lo);
        *(uint2*)&out[(size_t)k * 128 + c4]         = hi;
        *(uint2*)&out[(size_t)(128 + k) * 128 + c4] = lo;
    }
}

// ---------------------------------------------------------------------------
// HMMA helpers
// ---------------------------------------------------------------------------
__device__ __forceinline__ uint32_t smem_u32(const void* p) {
    uint32_t a;
    asm("{ .reg .u64 t; cvta.to.shared.u64 t, %1; cvt.u32.u64 %0, t; }"
        : "=r"(a) : "l"(p));
    return a;
}

__device__ __forceinline__ void ldsm4(uint32_t* r, uint32_t addr) {
    asm volatile("ldmatrix.sync.aligned.m8n8.x4.shared.b16 {%0,%1,%2,%3}, [%4];"
        : "=r"(r[0]), "=r"(r[1]), "=r"(r[2]), "=r"(r[3]) : "r"(addr));
}
__device__ __forceinline__ void ldsm4t(uint32_t* r, uint32_t addr) {
    asm volatile("ldmatrix.sync.aligned.m8n8.x4.trans.shared.b16 {%0,%1,%2,%3}, [%4];"
        : "=r"(r[0]), "=r"(r[1]), "=r"(r[2]), "=r"(r[3]) : "r"(addr));
}
__device__ __forceinline__ void mma16816(float* d, const uint32_t* a, const uint32_t* b) {
    asm volatile(
        "mma.sync.aligned.m16n8k16.row.col.f32.bf16.bf16.f32 "
        "{%0,%1,%2,%3}, {%4,%5,%6,%7}, {%8,%9}, {%0,%1,%2,%3};"
        : "+f"(d[0]), "+f"(d[1]), "+f"(d[2]), "+f"(d[3])
        : "r"(a[0]), "r"(a[1]), "r"(a[2]), "r"(a[3]), "r"(b[0]), "r"(b[1]));
}

// ---------------------------------------------------------------------------
// SMEM layout (XOR-swizzled, no padding):
//  A_s: 192 rows x 512B (256 bf16: hi k0..127, lo k128..255).
//       addr = r*512 + ((chunk ^ (r&7))<<4) + within ; chunk = byte>>4
//  B_s: 2 buffers, each 256 rows x 256B (128 bf16).
//       addr = k*256 + ((chunk ^ (k&7))<<4)
// ---------------------------------------------------------------------------
#define SM_A     0
#define SM_B0    98304
#define SM_B1    163840
#define SM_BIAS  229376
#define SMEM_BYTES (229376 + 512)

// ---------------------------------------------------------------------------
// Tensor-core (mma.sync bf16x3 split, merged k-loop) 4-way GEMM.
// One CTA = 384 rows (2 chunks of 192), 4 weights = 8 steps; B double-buffered
// via cp.async prefetch; 131 CTAs = ONE wave. 768 threads (24 warps):
// warp tile 32x32: rg = wid%6 (rows), cg = wid/6 (cols).
// ---------------------------------------------------------------------------
__global__ void __launch_bounds__(NT_G, 1) gemm_hmma_kernel(
    const float* __restrict__ A, const __nv_bfloat16* __restrict__ Bsp,
    OutArgs oa, int apply_relu)
{
    extern __shared__ char smem[];
    char* A_s = smem + SM_A;
    float* bias_s = (float*)(smem + SM_BIAS);

    const int t = threadIdx.x;
    const int wid = t >> 5;
    const int ln = t & 31;
    const int rg = wid % 6;        // rows rg*32 .. +31 within chunk
    const int cg = wid / 6;        // cols cg*32 .. +31

    if (t < 128) bias_s[t] = oa.bias[t];

    const uint32_t sbA  = smem_u32(smem + SM_A);
    const uint32_t sbB0 = smem_u32(smem + SM_B0);
    const uint32_t sbB1 = smem_u32(smem + SM_B1);

    // ---- prologue: prefetch B for step 0 (weight 0) into buf0 ----
    {
        const char* src = (const char*)Bsp;
        #pragma unroll
        for (int l = 0; l < 6; l++) {
            int idx = l * NT_G + t;
            if (idx < 4096) {
                int r = idx >> 4, q = idx & 15;
                uint32_t sa = sbB0 + (uint32_t)(r * 256 + ((q ^ (r & 7)) << 4));
                asm volatile("cp.async.cg.shared.global [%0], [%1], 16;"
                             :: "r"(sa), "l"(src + r * 256 + q * 16) : "memory");
            }
        }
        asm volatile("cp.async.commit_group;" ::: "memory");
    }

    // ---- A convert for chunk c: f32 -> relu? -> bf16 split, swizzled ----
    auto convertA = [&](int c) {
        const int row0 = blockIdx.x * RPC + c * CHUNK;
        #pragma unroll 4
        for (int l = 0; l < 8; l++) {
            int idx = l * NT_G + t;          // 6144 float4 tasks
            int r = idx >> 5;
            int c4 = (idx & 31) * 4;
            int grow = row0 + r;
            float4 v = make_float4(0.f, 0.f, 0.f, 0.f);
            if (grow < NN) v = *(const float4*)&A[(size_t)grow * DD + c4];
            if (apply_relu) {
                v.x = fmaxf(v.x, 0.f); v.y = fmaxf(v.y, 0.f);
                v.z = fmaxf(v.z, 0.f); v.w = fmaxf(v.w, 0.f);
            }
            uint2 hi, lo;
            split4(v, hi, lo);
            int qh = c4 >> 3;                 // hi chunk (0..15)
            int off = (c4 & 7) * 2;           // 0 or 8
            int base = r * 512;
            int sw = r & 7;
            *(uint2*)(A_s + base + ((qh ^ sw) << 4) + off)        = hi;
            *(uint2*)(A_s + base + (((qh + 16) ^ sw) << 4) + off) = lo;
        }
    };
    convertA(0);

    // ---- per-lane ldsm bases ----
    const int mat = ln >> 3, rowin = ln & 7;
    // B: per np (col half), chunk q = cg*4 + np*2 + (mat>>1); row = kB + (mat&1)*8 + rowin
    uint32_t b_lane[2];
    #pragma unroll
    for (int np = 0; np < 2; np++) {
        int q = cg * 4 + np * 2 + (mat >> 1);
        b_lane[np] = (uint32_t)((((mat & 1) * 8 + rowin) * 256) + ((q ^ rowin) << 4));
    }
    // A: row rr = rg*32 + mi*16 + (ln&15); chunk q = 2*ks + (ln>>4) (+16 for lo)
    const uint32_t a_row_base = (uint32_t)((rg * 32 + (ln & 15)) * 512);
    const int axor = ln & 7;
    const int ahalf = ln >> 4;

    // ---- 8 steps: s = c*4 + w ----
    for (int s = 0; s < 8; s++) {
        const int c = s >> 2, w = s & 3;
        if (s == 4) convertA(1);

        // prefetch B for step s+1 into the other buffer
        if (s < 7) {
            const char* src = (const char*)Bsp + (size_t)((s + 1) & 3) * 65536;
            uint32_t dbuf = ((s + 1) & 1) ? sbB1 : sbB0;
            #pragma unroll
            for (int l = 0; l < 6; l++) {
                int idx = l * NT_G + t;
                if (idx < 4096) {
                    int r = idx >> 4, q = idx & 15;
                    uint32_t sa = dbuf + (uint32_t)(r * 256 + ((q ^ (r & 7)) << 4));
                    asm volatile("cp.async.cg.shared.global [%0], [%1], 16;"
                                 :: "r"(sa), "l"(src + r * 256 + q * 16) : "memory");
                }
            }
            asm volatile("cp.async.commit_group;" ::: "memory");
            asm volatile("cp.async.wait_group 1;" ::: "memory");
        } else {
            asm volatile("cp.async.wait_group 0;" ::: "memory");
        }
        __syncthreads();   // B(s) visible; A chunk (if rewritten) visible

        const uint32_t bbuf = (s & 1) ? sbB1 : sbB0;

        float ac[2][4][4];
        #pragma unroll
        for (int mi = 0; mi < 2; mi++)
            #pragma unroll
            for (int nt = 0; nt < 4; nt++)
                #pragma unroll
                for (int j = 0; j < 4; j++) ac[mi][nt][j] = 0.f;

        // ---- merged k-loop ----
        #pragma unroll
        for (int ks = 0; ks < 8; ks++) {
            uint32_t ahi[2][4], alo[2][4], bhi[2][4], blo[2][4];
            #pragma unroll
            for (int np = 0; np < 2; np++) {
                ldsm4t(bhi[np], bbuf + b_lane[np] + (uint32_t)(ks * 16 * 256));
                ldsm4t(blo[np], bbuf + b_lane[np] + (uint32_t)((128 + ks * 16) * 256));
            }
            #pragma unroll
            for (int mi = 0; mi < 2; mi++) {
                int qh = 2 * ks + ahalf;
                uint32_t rbase = sbA + a_row_base + (uint32_t)(mi * 16 * 512);
                ldsm4(ahi[mi], rbase + (uint32_t)((qh ^ axor) << 4));
                ldsm4(alo[mi], rbase + (uint32_t)(((qh + 16) ^ axor) << 4));
            }
            #pragma unroll
            for (int mi = 0; mi < 2; mi++)
                #pragma unroll
                for (int np = 0; np < 2; np++) {
                    mma16816(ac[mi][2 * np],     ahi[mi], &bhi[np][0]);
                    mma16816(ac[mi][2 * np + 1], ahi[mi], &bhi[np][2]);
                    mma16816(ac[mi][2 * np],     alo[mi], &bhi[np][0]);
                    mma16816(ac[mi][2 * np + 1], alo[mi], &bhi[np][2]);
                    mma16816(ac[mi][2 * np],     ahi[mi], &blo[np][0]);
                    mma16816(ac[mi][2 * np + 1], ahi[mi], &blo[np][2]);
                }
        }

        // ---- epilogue for (c, w) ----
        float* dst = oa.dst[w];
        const int r_base = blockIdx.x * RPC + c * CHUNK + rg * 32 + (ln >> 2);
        const int c_base = cg * 32 + (ln & 3) * 2;
        const bool add_bias = (w == 3);
        #pragma unroll
        for (int mi = 0; mi < 2; mi++) {
            const int r_m = r_base + mi * 16;
            #pragma unroll
            for (int nt = 0; nt < 4; nt++) {
                const int cc = c_base + nt * 8;
                float b0 = 0.f, b1 = 0.f;
                if (add_bias) { b0 = bias_s[cc]; b1 = bias_s[cc + 1]; }
                if (r_m < NN)
                    *(float2*)&dst[(size_t)r_m * DD + cc] =
                        make_float2(ac[mi][nt][0] + b0, ac[mi][nt][1] + b1);
                if (r_m + 8 < NN)
                    *(float2*)&dst[(size_t)(r_m + 8) * DD + cc] =
                        make_float2(ac[mi][nt][2] + b0, ac[mi][nt][3] + b1);
            }
        }
        __syncthreads();   // all warps done with buf/A_s before overwrite
    }
}

// ---------------------------------------------------------------------------
// Edge kernel: one warp per TWO edges (batched gathers for 2x MLP).
//   eta = sigmoid(K[tgt] + Q[src]); msg = eta * V[src]; red.v4 into out[tgt]
// ---------------------------------------------------------------------------
__global__ void __launch_bounds__(256) edge_kernel(
    const void* __restrict__ edge_index,
    const float* __restrict__ K, const float* __restrict__ Q,
    const float* __restrict__ V, float* __restrict__ out)
{
    int warp = (blockIdx.x * blockDim.x + threadIdx.x) >> 5;
    int e0 = warp * 2;
    if (e0 >= NE) return;
    int lane = threadIdx.x & 31;
    int d0 = lane * 4;

    int src0, tgt0, src1, tgt1;
    if (g_is32) {
        const int* ei = (const int*)edge_index;
        src0 = ei[e0];      src1 = ei[e0 + 1];
        tgt0 = ei[NE + e0]; tgt1 = ei[NE + e0 + 1];
    } else {
        const long long* ei = (const long long*)edge_index;
        src0 = (int)ei[e0];      src1 = (int)ei[e0 + 1];
        tgt0 = (int)ei[NE + e0]; tgt1 = (int)ei[NE + e0 + 1];
    }

    float4 kt0 = *(const float4*)&K[(size_t)tgt0 * DD + d0];
    float4 qs0 = *(const float4*)&Q[(size_t)src0 * DD + d0];
    float4 vs0 = *(const float4*)&V[(size_t)src0 * DD + d0];
    float4 kt1 = *(const float4*)&K[(size_t)tgt1 * DD + d0];
    float4 qs1 = *(const float4*)&Q[(size_t)src1 * DD + d0];
    float4 vs1 = *(const float4*)&V[(size_t)src1 * DD + d0];

    float4 m0, m1;
    m0.x = vs0.x / (1.f + __expf(-(kt0.x + qs0.x)));
    m0.y = vs0.y / (1.f + __expf(-(kt0.y + qs0.y)));
    m0.z = vs0.z / (1.f + __expf(-(kt0.z + qs0.z)));
    m0.w = vs0.w / (1.f + __expf(-(kt0.w + qs0.w)));
    m1.x = vs1.x / (1.f + __expf(-(kt1.x + qs1.x)));
    m1.y = vs1.y / (1.f + __expf(-(kt1.y + qs1.y)));
    m1.z = vs1.z / (1.f + __expf(-(kt1.z + qs1.z)));
    m1.w = vs1.w / (1.f + __expf(-(kt1.w + qs1.w)));

    float* o0 = &out[(size_t)tgt0 * DD + d0];
    asm volatile("red.global.add.v4.f32 [%0], {%1, %2, %3, %4};"
                 :: "l"(o0), "f"(m0.x), "f"(m0.y), "f"(m0.z), "f"(m0.w)
                 : "memory");
    float* o1 = &out[(size_t)tgt1 * DD + d0];
    asm volatile("red.global.add.v4.f32 [%0], {%1, %2, %3, %4};"
                 :: "l"(o1), "f"(m1.x), "f"(m1.y), "f"(m1.z), "f"(m1.w)
                 : "memory");
}

// ---------------------------------------------------------------------------
extern "C" void kernel_launch(void* const* d_in, const int* in_sizes, int n_in,
                              void* d_out, int out_size)
{
    const float* x   = (const float*)d_in[0];
    const void*  ei  = d_in[1];
    const float* Wk1 = (const float*)d_in[2];
    const float* Wq1 = (const float*)d_in[3];
    const float* Wv1 = (const float*)d_in[4];
    const float* Ws1 = (const float*)d_in[5];
    const float* b1  = (const float*)d_in[6];
    const float* Wk2 = (const float*)d_in[7];
    const float* Wq2 = (const float*)d_in[8];
    const float* Wv2 = (const float*)d_in[9];
    const float* Ws2 = (const float*)d_in[10];
    const float* b2  = (const float*)d_in[11];
    float* out = (float*)d_out;

    float *pK, *pQ, *pV, *pH;
    __nv_bfloat16* pBs;
    cudaGetSymbolAddress((void**)&pK, g_K);
    cudaGetSymbolAddress((void**)&pQ, g_Q);
    cudaGetSymbolAddress((void**)&pV, g_V);
    cudaGetSymbolAddress((void**)&pH, g_H);
    cudaGetSymbolAddress((void**)&pBs, g_Bs);

    cudaFuncSetAttribute(gemm_hmma_kernel,
                         cudaFuncAttributeMaxDynamicSharedMemorySize, SMEM_BYTES);

    detect_init_kernel<<<1, 1>>>();
    detect_kernel<<<(NE + 255) / 256, 256>>>((const unsigned int*)ei);

    PrepArgs pa;
    pa.W[0] = Wk1; pa.W[1] = Wq1; pa.W[2] = Wv1; pa.W[3] = Ws1;
    pa.W[4] = Wk2; pa.W[5] = Wq2; pa.W[6] = Wv2; pa.W[7] = Ws2;
    prep_weights<<<8, 256>>>(pa);

    dim3 ggrid((NN + RPC - 1) / RPC);        // 131 CTAs = one wave
    dim3 egrid((NE / 2 * 32 + 255) / 256);   // one warp per 2 edges

    // ---- Layer 1 ----
    OutArgs o1;
    o1.dst[0] = pK; o1.dst[1] = pQ; o1.dst[2] = pV; o1.dst[3] = pH;
    o1.bias = b1;
    gemm_hmma_kernel<<<ggrid, NT_G, SMEM_BYTES>>>(x, pBs, o1, /*relu=*/0);
    edge_kernel<<<egrid, 256>>>(ei, pK, pQ, pV, pH);

    // ---- Layer 2 (ReLU fused into A convert) ----
    OutArgs o2;
    o2.dst[0] = pK; o2.dst[1] = pQ; o2.dst[2] = pV; o2.dst[3] = out;
    o2.bias = b2;
    gemm_hmma_kernel<<<ggrid, NT_G, SMEM_BYTES>>>(pH, pBs + (size_t)4 * 256 * 128, o2, /*relu=*/1);
    edge_kernel<<<egrid, 256>>>(ei, pK, pQ, pV, out);
}